// round 11
// baseline (speedup 1.0000x reference)
#include <cuda_runtime.h>
#include <cstdint>

// ---------------------------------------------------------------------------
// DirectedEdgeEncoder: out[E,128] = relu(concat(x[row[e]], edge_attr[e]) @ W^T + b)
// Family-portable tensor path (sm_103 PTX target has no tcgen05):
// mma.sync m16n8k16 bf16, fp32 accum, 3-pass hi/lo split for fp32 accuracy.
// Persistent CTAs, register-prefetch software pipeline.
// ---------------------------------------------------------------------------

#define NT 256
#define LDA_B 272                 // bytes per bf16 tile row (136 bf16: 128 + 8 pad)
#define TILE_B (128 * LDA_B)      // 34816 B per operand tile
#define OFF_AHI 0
#define OFF_ALO (TILE_B)
#define OFF_WHI (2 * TILE_B)
#define OFF_WLO (3 * TILE_B)
#define SMEM_BYTES (4 * TILE_B)   // 139264 B

static __device__ __forceinline__ uint32_t smem_u32(const void* p) {
    uint32_t a;
    asm("{ .reg .u64 t; cvta.to.shared.u64 t, %1; cvt.u32.u64 %0, t; }"
        : "=r"(a) : "l"(p));
    return a;
}

// pack two f32 -> bf16x2 (RN): 'e' in low 16 bits (even k), 'o' in high (odd k)
static __device__ __forceinline__ uint32_t pack_bf16x2(float e, float o) {
    uint32_t r;
    asm("cvt.rn.bf16x2.f32 %0, %1, %2;" : "=r"(r) : "f"(o), "f"(e));
    return r;
}

// split (e,o) into bf16 hi word + bf16 lo (residual) word
static __device__ __forceinline__ void cvt2(float e, float o,
                                            uint32_t& hw, uint32_t& lw) {
    hw = pack_bf16x2(e, o);
    float fe = __uint_as_float(hw << 16);           // bf16(e) as f32
    float fo = __uint_as_float(hw & 0xFFFF0000u);   // bf16(o) as f32
    lw = pack_bf16x2(e - fe, o - fo);
}

#define LDSM4(r, addr)                                                        \
    asm volatile("ldmatrix.sync.aligned.m8n8.x4.shared.b16 {%0,%1,%2,%3}, [%4];" \
                 : "=r"((r)[0]), "=r"((r)[1]), "=r"((r)[2]), "=r"((r)[3])     \
                 : "r"(addr))

#define MMA_BF16(d, a, b0, b1)                                                \
    asm volatile("mma.sync.aligned.m16n8k16.row.col.f32.bf16.bf16.f32 "       \
                 "{%0,%1,%2,%3}, {%4,%5,%6,%7}, {%8,%9}, {%0,%1,%2,%3};"      \
                 : "+f"((d)[0]), "+f"((d)[1]), "+f"((d)[2]), "+f"((d)[3])     \
                 : "r"((a)[0]), "r"((a)[1]), "r"((a)[2]), "r"((a)[3]),        \
                   "r"(b0), "r"(b1))

// gather/stream one tile's fp32 data into registers (2 float4 per row-chunk)
static __device__ __forceinline__ void prefetch_tile(
    const float* __restrict__ x, const float* __restrict__ ea,
    const int* __restrict__ e32, const long long* __restrict__ e64,
    bool is64, int E, int e0, int g, int rbase, int k0,
    float4* va, float4* vb)
{
    #pragma unroll
    for (int i = 0; i < 8; ++i) {
        int r = rbase + (i << 4);
        int e = e0 + r;
        if (e < E) {
            const float4* s;
            if (g < 8) {
                long long ri = is64 ? e64[e] : (long long)e32[e];
                s = (const float4*)(x + (ri << 6) + k0);
            } else {
                s = (const float4*)(ea + (((size_t)e) << 6) + (k0 - 64));
            }
            va[i] = s[0];
            vb[i] = s[1];
        } else {
            va[i] = make_float4(0.f, 0.f, 0.f, 0.f);
            vb[i] = va[i];
        }
    }
}

// convert registers -> bf16 hi/lo tiles in SMEM (padded row layout)
static __device__ __forceinline__ void store_tile(
    char* smem, int hi_off, int lo_off, int rbase, int k0,
    const float4* va, const float4* vb)
{
    #pragma unroll
    for (int i = 0; i < 8; ++i) {
        int r = rbase + (i << 4);
        uint32_t h[4], l[4];
        cvt2(va[i].x, va[i].y, h[0], l[0]);
        cvt2(va[i].z, va[i].w, h[1], l[1]);
        cvt2(vb[i].x, vb[i].y, h[2], l[2]);
        cvt2(vb[i].z, vb[i].w, h[3], l[3]);
        int off = r * LDA_B + (k0 << 1);
        *(uint4*)(smem + hi_off + off) = make_uint4(h[0], h[1], h[2], h[3]);
        *(uint4*)(smem + lo_off + off) = make_uint4(l[0], l[1], l[2], l[3]);
    }
}

__global__ void __launch_bounds__(NT, 1)
edge_enc_kernel(const float* __restrict__ x,
                const float* __restrict__ ea,
                const void*  __restrict__ eidx_raw,
                const float* __restrict__ W,
                const float* __restrict__ bias,
                float* __restrict__ out,
                int E)
{
    extern __shared__ __align__(1024) char smem[];
    const int tid  = threadIdx.x;
    const int lane = tid & 31;
    const int wid  = tid >> 5;
    const uint32_t sb = smem_u32(smem);

    // index dtype sniff: int64 entries (values < 50000) have zero high words
    const int* e32 = (const int*)eidx_raw;
    const long long* e64 = (const long long*)eidx_raw;
    const bool is64 = ((e32[1] | e32[3] | e32[5] | e32[7]) == 0);

    const int g = tid & 15;          // k-group: 8 floats starting at k0
    const int k0 = g << 3;
    const int rbase = tid >> 4;      // row base (stride 16)

    // ---- build static W hi/lo tiles ([n=128][k=128], k-contiguous) ---------
    {
        float4 wa[8], wb[8];
        #pragma unroll
        for (int i = 0; i < 8; ++i) {
            int r = rbase + (i << 4);
            const float4* s = (const float4*)(W + r * 128 + k0);
            wa[i] = s[0];
            wb[i] = s[1];
        }
        store_tile(smem, OFF_WHI, OFF_WLO, rbase, k0, wa, wb);
    }

    // warp tiling: 2 (m) x 4 (n); warp tile 64m x 32n
    const int wm = wid & 1;
    const int wn = wid >> 1;

    // per-thread ldmatrix row offsets (within a 16x16 / 8x16-pair footprint)
    const uint32_t a_off = (uint32_t)((lane & 15) * LDA_B + ((lane >> 4) << 4));
    const uint32_t b_off = (uint32_t)(((lane & 7) + ((lane >> 4) << 3)) * LDA_B
                                      + (((lane >> 3) & 1) << 4));
    const uint32_t aA = sb + (uint32_t)(wm * 64 * LDA_B) + a_off;
    const uint32_t aB = sb + (uint32_t)(wn * 32 * LDA_B) + b_off;

    // bias fragment (col layout of the D fragment)
    const int col0 = wn * 32 + 2 * (lane & 3);
    float bl[4][2];
    #pragma unroll
    for (int nf = 0; nf < 4; ++nf) {
        bl[nf][0] = bias[col0 + nf * 8];
        bl[nf][1] = bias[col0 + nf * 8 + 1];
    }

    const int ntiles = (E + 127) >> 7;

    // prefetch first tile
    float4 va[8], vb[8];
    if (blockIdx.x < ntiles)
        prefetch_tile(x, ea, e32, e64, is64, E, blockIdx.x << 7,
                      g, rbase, k0, va, vb);

    const uint32_t passA[3] = {OFF_AHI, OFF_ALO, OFF_AHI};
    const uint32_t passB[3] = {OFF_WHI, OFF_WHI, OFF_WLO};

    for (int t = blockIdx.x; t < ntiles; t += gridDim.x) {
        const int e0 = t << 7;

        // stage current tile (regs -> bf16 hi/lo SMEM)
        store_tile(smem, OFF_AHI, OFF_ALO, rbase, k0, va, vb);
        __syncthreads();

        // kick off next tile's global loads (hidden behind the MMA phase)
        const int tn = t + gridDim.x;
        if (tn < ntiles)
            prefetch_tile(x, ea, e32, e64, is64, E, tn << 7,
                          g, rbase, k0, va, vb);

        // ---- MMA: D = Ah*Wh^T + Al*Wh^T + Ah*Wl^T ---------------------------
        float acc[4][4][4];
        #pragma unroll
        for (int mf = 0; mf < 4; ++mf)
            #pragma unroll
            for (int nf = 0; nf < 4; ++nf)
                #pragma unroll
                for (int v = 0; v < 4; ++v)
                    acc[mf][nf][v] = 0.f;

        #pragma unroll
        for (int p = 0; p < 3; ++p) {
            const uint32_t pa = aA + passA[p];
            const uint32_t pb = aB + passB[p];
            #pragma unroll
            for (int ks = 0; ks < 8; ++ks) {
                uint32_t afr[4][4];
                #pragma unroll
                for (int mf = 0; mf < 4; ++mf)
                    LDSM4(afr[mf], pa + (uint32_t)(mf * 16 * LDA_B + ks * 32));
                uint32_t bfr[2][4];
                LDSM4(bfr[0], pb + (uint32_t)(ks * 32));
                LDSM4(bfr[1], pb + (uint32_t)(16 * LDA_B + ks * 32));
                #pragma unroll
                for (int mf = 0; mf < 4; ++mf)
                    #pragma unroll
                    for (int nf = 0; nf < 4; ++nf)
                        MMA_BF16(acc[mf][nf], afr[mf],
                                 bfr[nf >> 1][(nf & 1) * 2],
                                 bfr[nf >> 1][(nf & 1) * 2 + 1]);
            }
        }

        // ---- epilogue: +bias, relu, STG.64 ----------------------------------
        const int r0 = e0 + wm * 64 + (lane >> 2);
        #pragma unroll
        for (int mf = 0; mf < 4; ++mf) {
            const int ra = r0 + mf * 16;
            const int rbw = ra + 8;
            #pragma unroll
            for (int nf = 0; nf < 4; ++nf) {
                const int c = col0 + nf * 8;
                if (ra < E) {
                    float2 v;
                    v.x = fmaxf(acc[mf][nf][0] + bl[nf][0], 0.f);
                    v.y = fmaxf(acc[mf][nf][1] + bl[nf][1], 0.f);
                    *(float2*)(out + (size_t)ra * 128 + c) = v;
                }
                if (rbw < E) {
                    float2 v;
                    v.x = fmaxf(acc[mf][nf][2] + bl[nf][0], 0.f);
                    v.y = fmaxf(acc[mf][nf][3] + bl[nf][1], 0.f);
                    *(float2*)(out + (size_t)rbw * 128 + c) = v;
                }
            }
        }
        __syncthreads();   // all warps done reading A tiles before next store
    }
}

extern "C" void kernel_launch(void* const* d_in, const int* in_sizes, int n_in,
                              void* d_out, int out_size) {
    const float* x  = (const float*)d_in[0];
    const float* ea = (const float*)d_in[1];
    const void*  ei = (const void*)d_in[2];
    const float* W  = (const float*)d_in[3];
    const float* b  = (const float*)d_in[4];
    float* out = (float*)d_out;

    const int E = in_sizes[1] / 64;   // edge_attr is [E, 64]
    if (E <= 0) return;

    cudaFuncSetAttribute(edge_enc_kernel,
                         cudaFuncAttributeMaxDynamicSharedMemorySize, SMEM_BYTES);
    edge_enc_kernel<<<148, NT, SMEM_BYTES>>>(x, ea, ei, W, b, out, E);
}

// round 12
// speedup vs baseline: 1.0009x; 1.0009x over previous
#include <cuda_runtime.h>
#include <cstdint>

// ---------------------------------------------------------------------------
// DirectedEdgeEncoder: out[E,128] = relu(concat(x[row[e]], edge_attr[e]) @ W^T + b)
// Family-portable tensor path (sm_103 PTX target has no tcgen05):
// mma.sync m16n8k16 bf16, fp32 accum, 3-pass hi/lo split for fp32 accuracy.
// Persistent CTAs, register-prefetch software pipeline.
// ---------------------------------------------------------------------------

#define NT 256
#define LDA_B 272                 // bytes per bf16 tile row (136 bf16: 128 + 8 pad)
#define TILE_B (128 * LDA_B)      // 34816 B per operand tile
#define OFF_AHI 0
#define OFF_ALO (TILE_B)
#define OFF_WHI (2 * TILE_B)
#define OFF_WLO (3 * TILE_B)
#define SMEM_BYTES (4 * TILE_B)   // 139264 B

static __device__ __forceinline__ uint32_t smem_u32(const void* p) {
    uint32_t a;
    asm("{ .reg .u64 t; cvta.to.shared.u64 t, %1; cvt.u32.u64 %0, t; }"
        : "=r"(a) : "l"(p));
    return a;
}

// pack two f32 -> bf16x2 (RN): 'e' in low 16 bits (even k), 'o' in high (odd k)
static __device__ __forceinline__ uint32_t pack_bf16x2(float e, float o) {
    uint32_t r;
    asm("cvt.rn.bf16x2.f32 %0, %1, %2;" : "=r"(r) : "f"(o), "f"(e));
    return r;
}

// split (e,o) into bf16 hi word + bf16 lo (residual) word
static __device__ __forceinline__ void cvt2(float e, float o,
                                            uint32_t& hw, uint32_t& lw) {
    hw = pack_bf16x2(e, o);
    float fe = __uint_as_float(hw << 16);           // bf16(e) as f32
    float fo = __uint_as_float(hw & 0xFFFF0000u);   // bf16(o) as f32
    lw = pack_bf16x2(e - fe, o - fo);
}

#define LDSM4(r, addr)                                                        \
    asm volatile("ldmatrix.sync.aligned.m8n8.x4.shared.b16 {%0,%1,%2,%3}, [%4];" \
                 : "=r"((r)[0]), "=r"((r)[1]), "=r"((r)[2]), "=r"((r)[3])     \
                 : "r"(addr))

#define MMA_BF16(d, a, b0, b1)                                                \
    asm volatile("mma.sync.aligned.m16n8k16.row.col.f32.bf16.bf16.f32 "       \
                 "{%0,%1,%2,%3}, {%4,%5,%6,%7}, {%8,%9}, {%0,%1,%2,%3};"      \
                 : "+f"((d)[0]), "+f"((d)[1]), "+f"((d)[2]), "+f"((d)[3])     \
                 : "r"((a)[0]), "r"((a)[1]), "r"((a)[2]), "r"((a)[3]),        \
                   "r"(b0), "r"(b1))

// gather/stream one tile's fp32 data into registers (2 float4 per row-chunk)
static __device__ __forceinline__ void prefetch_tile(
    const float* __restrict__ x, const float* __restrict__ ea,
    const int* __restrict__ e32, const long long* __restrict__ e64,
    bool is64, int E, int e0, int g, int rbase, int k0,
    float4* va, float4* vb)
{
    #pragma unroll
    for (int i = 0; i < 8; ++i) {
        int r = rbase + (i << 4);
        int e = e0 + r;
        if (e < E) {
            const float4* s;
            if (g < 8) {
                long long ri = is64 ? e64[e] : (long long)e32[e];
                s = (const float4*)(x + (ri << 6) + k0);
            } else {
                s = (const float4*)(ea + (((size_t)e) << 6) + (k0 - 64));
            }
            va[i] = s[0];
            vb[i] = s[1];
        } else {
            va[i] = make_float4(0.f, 0.f, 0.f, 0.f);
            vb[i] = va[i];
        }
    }
}

// convert registers -> bf16 hi/lo tiles in SMEM (padded row layout)
static __device__ __forceinline__ void store_tile(
    char* smem, int hi_off, int lo_off, int rbase, int k0,
    const float4* va, const float4* vb)
{
    #pragma unroll
    for (int i = 0; i < 8; ++i) {
        int r = rbase + (i << 4);
        uint32_t h[4], l[4];
        cvt2(va[i].x, va[i].y, h[0], l[0]);
        cvt2(va[i].z, va[i].w, h[1], l[1]);
        cvt2(vb[i].x, vb[i].y, h[2], l[2]);
        cvt2(vb[i].z, vb[i].w, h[3], l[3]);
        int off = r * LDA_B + (k0 << 1);
        *(uint4*)(smem + hi_off + off) = make_uint4(h[0], h[1], h[2], h[3]);
        *(uint4*)(smem + lo_off + off) = make_uint4(l[0], l[1], l[2], l[3]);
    }
}

__global__ void __launch_bounds__(NT, 1)
edge_enc_kernel(const float* __restrict__ x,
                const float* __restrict__ ea,
                const void*  __restrict__ eidx_raw,
                const float* __restrict__ W,
                const float* __restrict__ bias,
                float* __restrict__ out,
                int E)
{
    extern __shared__ __align__(1024) char smem[];
    const int tid  = threadIdx.x;
    const int lane = tid & 31;
    const int wid  = tid >> 5;
    const uint32_t sb = smem_u32(smem);

    // index dtype sniff: int64 entries (values < 50000) have zero high words
    const int* e32 = (const int*)eidx_raw;
    const long long* e64 = (const long long*)eidx_raw;
    const bool is64 = ((e32[1] | e32[3] | e32[5] | e32[7]) == 0);

    const int g = tid & 15;          // k-group: 8 floats starting at k0
    const int k0 = g << 3;
    const int rbase = tid >> 4;      // row base (stride 16)

    // ---- build static W hi/lo tiles ([n=128][k=128], k-contiguous) ---------
    {
        float4 wa[8], wb[8];
        #pragma unroll
        for (int i = 0; i < 8; ++i) {
            int r = rbase + (i << 4);
            const float4* s = (const float4*)(W + r * 128 + k0);
            wa[i] = s[0];
            wb[i] = s[1];
        }
        store_tile(smem, OFF_WHI, OFF_WLO, rbase, k0, wa, wb);
    }

    // warp tiling: 2 (m) x 4 (n); warp tile 64m x 32n
    const int wm = wid & 1;
    const int wn = wid >> 1;

    // per-thread ldmatrix row offsets (within a 16x16 / 8x16-pair footprint)
    const uint32_t a_off = (uint32_t)((lane & 15) * LDA_B + ((lane >> 4) << 4));
    const uint32_t b_off = (uint32_t)(((lane & 7) + ((lane >> 4) << 3)) * LDA_B
                                      + (((lane >> 3) & 1) << 4));
    const uint32_t aA = sb + (uint32_t)(wm * 64 * LDA_B) + a_off;
    const uint32_t aB = sb + (uint32_t)(wn * 32 * LDA_B) + b_off;

    // bias fragment (col layout of the D fragment)
    const int col0 = wn * 32 + 2 * (lane & 3);
    float bl[4][2];
    #pragma unroll
    for (int nf = 0; nf < 4; ++nf) {
        bl[nf][0] = bias[col0 + nf * 8];
        bl[nf][1] = bias[col0 + nf * 8 + 1];
    }

    const int ntiles = (E + 127) >> 7;

    // prefetch first tile
    float4 va[8], vb[8];
    if (blockIdx.x < ntiles)
        prefetch_tile(x, ea, e32, e64, is64, E, blockIdx.x << 7,
                      g, rbase, k0, va, vb);

    const uint32_t passA[3] = {OFF_AHI, OFF_ALO, OFF_AHI};
    const uint32_t passB[3] = {OFF_WHI, OFF_WHI, OFF_WLO};

    for (int t = blockIdx.x; t < ntiles; t += gridDim.x) {
        const int e0 = t << 7;

        // stage current tile (regs -> bf16 hi/lo SMEM)
        store_tile(smem, OFF_AHI, OFF_ALO, rbase, k0, va, vb);
        __syncthreads();

        // kick off next tile's global loads (hidden behind the MMA phase)
        const int tn = t + gridDim.x;
        if (tn < ntiles)
            prefetch_tile(x, ea, e32, e64, is64, E, tn << 7,
                          g, rbase, k0, va, vb);

        // ---- MMA: D = Ah*Wh^T + Al*Wh^T + Ah*Wl^T ---------------------------
        float acc[4][4][4];
        #pragma unroll
        for (int mf = 0; mf < 4; ++mf)
            #pragma unroll
            for (int nf = 0; nf < 4; ++nf)
                #pragma unroll
                for (int v = 0; v < 4; ++v)
                    acc[mf][nf][v] = 0.f;

        #pragma unroll
        for (int p = 0; p < 3; ++p) {
            const uint32_t pa = aA + passA[p];
            const uint32_t pb = aB + passB[p];
            #pragma unroll
            for (int ks = 0; ks < 8; ++ks) {
                uint32_t afr[4][4];
                #pragma unroll
                for (int mf = 0; mf < 4; ++mf)
                    LDSM4(afr[mf], pa + (uint32_t)(mf * 16 * LDA_B + ks * 32));
                uint32_t bfr[2][4];
                LDSM4(bfr[0], pb + (uint32_t)(ks * 32));
                LDSM4(bfr[1], pb + (uint32_t)(16 * LDA_B + ks * 32));
                #pragma unroll
                for (int mf = 0; mf < 4; ++mf)
                    #pragma unroll
                    for (int nf = 0; nf < 4; ++nf)
                        MMA_BF16(acc[mf][nf], afr[mf],
                                 bfr[nf >> 1][(nf & 1) * 2],
                                 bfr[nf >> 1][(nf & 1) * 2 + 1]);
            }
        }

        // ---- epilogue: +bias, relu, STG.64 ----------------------------------
        const int r0 = e0 + wm * 64 + (lane >> 2);
        #pragma unroll
        for (int mf = 0; mf < 4; ++mf) {
            const int ra = r0 + mf * 16;
            const int rbw = ra + 8;
            #pragma unroll
            for (int nf = 0; nf < 4; ++nf) {
                const int c = col0 + nf * 8;
                if (ra < E) {
                    float2 v;
                    v.x = fmaxf(acc[mf][nf][0] + bl[nf][0], 0.f);
                    v.y = fmaxf(acc[mf][nf][1] + bl[nf][1], 0.f);
                    *(float2*)(out + (size_t)ra * 128 + c) = v;
                }
                if (rbw < E) {
                    float2 v;
                    v.x = fmaxf(acc[mf][nf][2] + bl[nf][0], 0.f);
                    v.y = fmaxf(acc[mf][nf][3] + bl[nf][1], 0.f);
                    *(float2*)(out + (size_t)rbw * 128 + c) = v;
                }
            }
        }
        __syncthreads();   // all warps done reading A tiles before next store
    }
}

extern "C" void kernel_launch(void* const* d_in, const int* in_sizes, int n_in,
                              void* d_out, int out_size) {
    const float* x  = (const float*)d_in[0];
    const float* ea = (const float*)d_in[1];
    const void*  ei = (const void*)d_in[2];
    const float* W  = (const float*)d_in[3];
    const float* b  = (const float*)d_in[4];
    float* out = (float*)d_out;

    const int E = in_sizes[1] / 64;   // edge_attr is [E, 64]
    if (E <= 0) return;

    cudaFuncSetAttribute(edge_enc_kernel,
                         cudaFuncAttributeMaxDynamicSharedMemorySize, SMEM_BYTES);
    edge_enc_kernel<<<148, NT, SMEM_BYTES>>>(x, ea, ei, W, b, out, E);
}

// round 13
// speedup vs baseline: 1.9012x; 1.8995x over previous
#include <cuda_runtime.h>
#include <cstdint>

// ---------------------------------------------------------------------------
// DirectedEdgeEncoder: out[E,128] = relu(concat(x[row[e]], edge_attr[e]) @ W^T + b)
// mma.sync m16n8k16 bf16 (sm_103-portable), fp32 accum, 3-term hi/lo split:
//   D = Ah*Wh + Al*Wh + Ah*Wl   (drops lo*lo, ~1.5e-5 rel)
// 512 threads, 4x4 warp grid (32x32 warp tiles), fused inner loop,
// double-buffered A smem, register-prefetch pipeline, persistent CTAs.
// ---------------------------------------------------------------------------

#define NT 512
#define LDA_B 272                 // bytes per bf16 tile row (136 bf16: 128 + 8 pad)
#define TILE_B (128 * LDA_B)      // 34816 B per operand tile
// A double buffer: buf p at p*2*TILE_B (hi), +TILE_B (lo). W at 4*TILE_B (hi), 5*TILE_B (lo).
#define OFF_W (4 * TILE_B)
#define SMEM_BYTES (6 * TILE_B)   // 208896 B

static __device__ __forceinline__ uint32_t smem_u32(const void* p) {
    uint32_t a;
    asm("{ .reg .u64 t; cvta.to.shared.u64 t, %1; cvt.u32.u64 %0, t; }"
        : "=r"(a) : "l"(p));
    return a;
}

// pack two f32 -> bf16x2 (RN): 'e' low half (even k), 'o' high half (odd k)
static __device__ __forceinline__ uint32_t pack_bf16x2(float e, float o) {
    uint32_t r;
    asm("cvt.rn.bf16x2.f32 %0, %1, %2;" : "=r"(r) : "f"(o), "f"(e));
    return r;
}

// split (e,o) into bf16 hi word + bf16 lo (residual) word
static __device__ __forceinline__ void cvt2(float e, float o,
                                            uint32_t& hw, uint32_t& lw) {
    hw = pack_bf16x2(e, o);
    float fe = __uint_as_float(hw << 16);           // bf16(e) as f32
    float fo = __uint_as_float(hw & 0xFFFF0000u);   // bf16(o) as f32
    lw = pack_bf16x2(e - fe, o - fo);
}

#define LDSM4(r, addr)                                                        \
    asm volatile("ldmatrix.sync.aligned.m8n8.x4.shared.b16 {%0,%1,%2,%3}, [%4];" \
                 : "=r"((r)[0]), "=r"((r)[1]), "=r"((r)[2]), "=r"((r)[3])     \
                 : "r"(addr))

#define MMA_BF16(d, a, b0, b1)                                                \
    asm volatile("mma.sync.aligned.m16n8k16.row.col.f32.bf16.bf16.f32 "       \
                 "{%0,%1,%2,%3}, {%4,%5,%6,%7}, {%8,%9}, {%0,%1,%2,%3};"      \
                 : "+f"((d)[0]), "+f"((d)[1]), "+f"((d)[2]), "+f"((d)[3])     \
                 : "r"((a)[0]), "r"((a)[1]), "r"((a)[2]), "r"((a)[3]),        \
                   "r"(b0), "r"(b1))

// gather/stream one tile's fp32 data into registers (4 rows x 8 floats/thread)
static __device__ __forceinline__ void prefetch_tile(
    const float* __restrict__ x, const float* __restrict__ ea,
    const int* __restrict__ e32, const long long* __restrict__ e64,
    bool is64, int E, int e0, int g, int rbase, int k0,
    float4* va, float4* vb)
{
    #pragma unroll
    for (int i = 0; i < 4; ++i) {
        int r = rbase + (i << 5);
        int e = e0 + r;
        if (e < E) {
            const float4* s;
            if (g < 8) {
                long long ri = is64 ? e64[e] : (long long)e32[e];
                s = (const float4*)(x + (ri << 6) + k0);
            } else {
                s = (const float4*)(ea + (((size_t)e) << 6) + (k0 - 64));
            }
            va[i] = s[0];
            vb[i] = s[1];
        } else {
            va[i] = make_float4(0.f, 0.f, 0.f, 0.f);
            vb[i] = va[i];
        }
    }
}

// convert registers -> bf16 hi/lo tiles in SMEM (padded row layout)
static __device__ __forceinline__ void store_tile(
    char* smem, int hi_off, int rbase, int k0,
    const float4* va, const float4* vb)
{
    #pragma unroll
    for (int i = 0; i < 4; ++i) {
        int r = rbase + (i << 5);
        uint32_t h[4], l[4];
        cvt2(va[i].x, va[i].y, h[0], l[0]);
        cvt2(va[i].z, va[i].w, h[1], l[1]);
        cvt2(vb[i].x, vb[i].y, h[2], l[2]);
        cvt2(vb[i].z, vb[i].w, h[3], l[3]);
        int off = r * LDA_B + (k0 << 1);
        *(uint4*)(smem + hi_off + off) = make_uint4(h[0], h[1], h[2], h[3]);
        *(uint4*)(smem + hi_off + TILE_B + off) = make_uint4(l[0], l[1], l[2], l[3]);
    }
}

__global__ void __launch_bounds__(NT, 1)
edge_enc_kernel(const float* __restrict__ x,
                const float* __restrict__ ea,
                const void*  __restrict__ eidx_raw,
                const float* __restrict__ W,
                const float* __restrict__ bias,
                float* __restrict__ out,
                int E)
{
    extern __shared__ __align__(1024) char smem[];
    const int tid  = threadIdx.x;
    const int lane = tid & 31;
    const int wid  = tid >> 5;
    const uint32_t sb = smem_u32(smem);

    // index dtype sniff: int64 entries (values < 50000) have zero high words
    const int* e32 = (const int*)eidx_raw;
    const long long* e64 = (const long long*)eidx_raw;
    const bool is64 = ((e32[1] | e32[3] | e32[5] | e32[7]) == 0);

    const int g  = tid & 15;         // k-group: 8 floats starting at k0
    const int k0 = g << 3;
    const int rbase = tid >> 4;      // row base 0..31 (stride 32)

    // ---- build static W hi/lo tiles ([n=128][k=128], k-contiguous) ---------
    {
        float4 wa[4], wb[4];
        #pragma unroll
        for (int i = 0; i < 4; ++i) {
            int r = rbase + (i << 5);
            const float4* s = (const float4*)(W + r * 128 + k0);
            wa[i] = s[0];
            wb[i] = s[1];
        }
        store_tile(smem, OFF_W, rbase, k0, wa, wb);
    }

    // warp tiling: 4 (m) x 4 (n); warp tile 32m x 32n
    const int wm = wid & 3;
    const int wn = wid >> 2;

    // per-thread ldmatrix offsets
    const uint32_t a_off = (uint32_t)((lane & 15) * LDA_B + ((lane >> 4) << 4));
    const uint32_t b_off = (uint32_t)(((lane & 7) + ((lane >> 4) << 3)) * LDA_B
                                      + (((lane >> 3) & 1) << 4));
    const uint32_t aA = (uint32_t)(wm * 32 * LDA_B) + a_off;              // + buf base
    const uint32_t aB = sb + OFF_W + (uint32_t)(wn * 32 * LDA_B) + b_off; // W is static

    // bias fragment (col layout of the D fragment)
    const int col0 = wn * 32 + 2 * (lane & 3);
    float bl[4][2];
    #pragma unroll
    for (int nf = 0; nf < 4; ++nf) {
        bl[nf][0] = bias[col0 + nf * 8];
        bl[nf][1] = bias[col0 + nf * 8 + 1];
    }

    const int ntiles = (E + 127) >> 7;

    // prefetch first tile
    float4 va[4], vb[4];
    if (blockIdx.x < ntiles)
        prefetch_tile(x, ea, e32, e64, is64, E, blockIdx.x << 7,
                      g, rbase, k0, va, vb);

    int p = 0;
    for (int t = blockIdx.x; t < ntiles; t += gridDim.x) {
        const int e0 = t << 7;
        const int bufo = p * 2 * TILE_B;

        // stage current tile (regs -> bf16 hi/lo SMEM, buffer p)
        store_tile(smem, bufo, rbase, k0, va, vb);
        __syncthreads();

        // kick off next tile's global loads (hidden behind the MMA phase)
        const int tn = t + gridDim.x;
        if (tn < ntiles)
            prefetch_tile(x, ea, e32, e64, is64, E, tn << 7,
                          g, rbase, k0, va, vb);

        // ---- fused MMA: D = Ah*Wh^T + Al*Wh^T + Ah*Wl^T ---------------------
        float acc[2][4][4];
        #pragma unroll
        for (int mf = 0; mf < 2; ++mf)
            #pragma unroll
            for (int nf = 0; nf < 4; ++nf)
                #pragma unroll
                for (int v = 0; v < 4; ++v)
                    acc[mf][nf][v] = 0.f;

        const uint32_t pa = sb + (uint32_t)bufo + aA;
        #pragma unroll
        for (int ks = 0; ks < 8; ++ks) {
            uint32_t ah[2][4], al[2][4], bh[2][4], blo[2][4];
            #pragma unroll
            for (int mf = 0; mf < 2; ++mf) {
                const uint32_t ao = pa + (uint32_t)(mf * 16 * LDA_B + ks * 32);
                LDSM4(ah[mf], ao);
                LDSM4(al[mf], ao + TILE_B);
            }
            LDSM4(bh[0],  aB + (uint32_t)(ks * 32));
            LDSM4(bh[1],  aB + (uint32_t)(16 * LDA_B + ks * 32));
            LDSM4(blo[0], aB + (uint32_t)(TILE_B + ks * 32));
            LDSM4(blo[1], aB + (uint32_t)(TILE_B + 16 * LDA_B + ks * 32));
            #pragma unroll
            for (int mf = 0; mf < 2; ++mf)
                #pragma unroll
                for (int nf = 0; nf < 4; ++nf) {
                    const uint32_t b0h = bh[nf >> 1][(nf & 1) * 2];
                    const uint32_t b1h = bh[nf >> 1][(nf & 1) * 2 + 1];
                    MMA_BF16(acc[mf][nf], ah[mf], b0h, b1h);
                    MMA_BF16(acc[mf][nf], al[mf], b0h, b1h);
                    MMA_BF16(acc[mf][nf], ah[mf],
                             blo[nf >> 1][(nf & 1) * 2],
                             blo[nf >> 1][(nf & 1) * 2 + 1]);
                }
        }

        // ---- epilogue: +bias, relu, STG.64 ----------------------------------
        const int r0 = e0 + wm * 32 + (lane >> 2);
        #pragma unroll
        for (int mf = 0; mf < 2; ++mf) {
            const int ra  = r0 + mf * 16;
            const int rbw = ra + 8;
            #pragma unroll
            for (int nf = 0; nf < 4; ++nf) {
                const int c = col0 + nf * 8;
                if (ra < E) {
                    float2 v;
                    v.x = fmaxf(acc[mf][nf][0] + bl[nf][0], 0.f);
                    v.y = fmaxf(acc[mf][nf][1] + bl[nf][1], 0.f);
                    *(float2*)(out + (size_t)ra * 128 + c) = v;
                }
                if (rbw < E) {
                    float2 v;
                    v.x = fmaxf(acc[mf][nf][2] + bl[nf][0], 0.f);
                    v.y = fmaxf(acc[mf][nf][3] + bl[nf][1], 0.f);
                    *(float2*)(out + (size_t)rbw * 128 + c) = v;
                }
            }
        }
        p ^= 1;
        // no trailing sync: next iteration writes the OTHER buffer, and the
        // collective sync above already proves all warps finished reading it.
    }
}

extern "C" void kernel_launch(void* const* d_in, const int* in_sizes, int n_in,
                              void* d_out, int out_size) {
    const float* x  = (const float*)d_in[0];
    const float* ea = (const float*)d_in[1];
    const void*  ei = (const void*)d_in[2];
    const float* W  = (const float*)d_in[3];
    const float* b  = (const float*)d_in[4];
    float* out = (float*)d_out;

    const int E = in_sizes[1] / 64;   // edge_attr is [E, 64]
    if (E <= 0) return;

    cudaFuncSetAttribute(edge_enc_kernel,
                         cudaFuncAttributeMaxDynamicSharedMemorySize, SMEM_BYTES);
    edge_enc_kernel<<<148, NT, SMEM_BYTES>>>(x, ea, ei, W, b, out, E);
}

// round 14
// speedup vs baseline: 2.0236x; 1.0644x over previous
#include <cuda_runtime.h>
#include <cstdint>

// ---------------------------------------------------------------------------
// DirectedEdgeEncoder: out[E,128] = relu(concat(x[row[e]], edge_attr[e]) @ W^T + b)
// Split: U = x @ W1^T + b  (N=50k rows, tiny GEMM, L2-resident scratch)
//        out[e] = relu(ea[e] @ W2^T + U[row[e]])   (K=64 GEMM + L2 gather)
// mma.sync m16n8k16 bf16 (sm_103-portable), fp32 accum, 3-term hi/lo split:
//   D = Ah*Wh + Al*Wh + Ah*Wl   (drops lo*lo, ~1e-5 rel)
// ---------------------------------------------------------------------------

#define NT 512
#define LDA_B 144                 // bytes per bf16 tile row (64 bf16 = 128B + 16 pad)
#define TILE_B (128 * LDA_B)      // 18432 B per operand tile (128 rows x 64 k)

// kernel-2 smem: A double buffer (hi+lo) + static W2 (hi+lo)
#define K2_AHI(p) ((p) * 2 * TILE_B)
#define K2_WHI    (4 * TILE_B)
#define K2_SMEM   (6 * TILE_B)    // 110592 B
// kernel-1 smem: single A (hi+lo) + W1 (hi+lo)
#define K1_AHI 0
#define K1_WHI (2 * TILE_B)
#define K1_SMEM (4 * TILE_B)      // 73728 B

#define U_MAX_ROWS 65536
__device__ float U_buf[(size_t)U_MAX_ROWS * 128];

static __device__ __forceinline__ uint32_t smem_u32(const void* p) {
    uint32_t a;
    asm("{ .reg .u64 t; cvta.to.shared.u64 t, %1; cvt.u32.u64 %0, t; }"
        : "=r"(a) : "l"(p));
    return a;
}

// pack two f32 -> bf16x2 (RN): 'e' low half (even k), 'o' high half (odd k)
static __device__ __forceinline__ uint32_t pack_bf16x2(float e, float o) {
    uint32_t r;
    asm("cvt.rn.bf16x2.f32 %0, %1, %2;" : "=r"(r) : "f"(o), "f"(e));
    return r;
}

// split (e,o) into bf16 hi word + bf16 lo (residual) word
static __device__ __forceinline__ void cvt2(float e, float o,
                                            uint32_t& hw, uint32_t& lw) {
    hw = pack_bf16x2(e, o);
    float fe = __uint_as_float(hw << 16);
    float fo = __uint_as_float(hw & 0xFFFF0000u);
    lw = pack_bf16x2(e - fe, o - fo);
}

#define LDSM4(r, addr)                                                        \
    asm volatile("ldmatrix.sync.aligned.m8n8.x4.shared.b16 {%0,%1,%2,%3}, [%4];" \
                 : "=r"((r)[0]), "=r"((r)[1]), "=r"((r)[2]), "=r"((r)[3])     \
                 : "r"(addr))

#define MMA_BF16(d, a, b0, b1)                                                \
    asm volatile("mma.sync.aligned.m16n8k16.row.col.f32.bf16.bf16.f32 "       \
                 "{%0,%1,%2,%3}, {%4,%5,%6,%7}, {%8,%9}, {%0,%1,%2,%3};"      \
                 : "+f"((d)[0]), "+f"((d)[1]), "+f"((d)[2]), "+f"((d)[3])     \
                 : "r"((a)[0]), "r"((a)[1]), "r"((a)[2]), "r"((a)[3]),        \
                   "r"(b0), "r"(b1))

// convert 2 float4 (8 consecutive k-values of one row) -> bf16 hi/lo in SMEM
static __device__ __forceinline__ void store_row8(char* smem, int hi_off,
                                                  int r, int k0,
                                                  float4 a, float4 b) {
    uint32_t h[4], l[4];
    cvt2(a.x, a.y, h[0], l[0]);
    cvt2(a.z, a.w, h[1], l[1]);
    cvt2(b.x, b.y, h[2], l[2]);
    cvt2(b.z, b.w, h[3], l[3]);
    int off = r * LDA_B + (k0 << 1);
    *(uint4*)(smem + hi_off + off) = make_uint4(h[0], h[1], h[2], h[3]);
    *(uint4*)(smem + hi_off + TILE_B + off) = make_uint4(l[0], l[1], l[2], l[3]);
}

// stage a [128 x 64] fp32 W slice (row stride 128 floats) as bf16 hi/lo tiles
static __device__ __forceinline__ void stage_w(char* smem, int hi_off,
                                               const float* __restrict__ Wsl,
                                               int tid) {
    const int g = tid & 7, k0 = g << 3;
    const int r0 = tid >> 3;           // 0..63
    #pragma unroll
    for (int i = 0; i < 2; ++i) {
        int r = r0 + (i << 6);
        const float4* s = (const float4*)(Wsl + r * 128 + k0);
        store_row8(smem, hi_off, r, k0, s[0], s[1]);
    }
}

// ---------------------------------------------------------------------------
// Kernel 1: U[n, :] = x[n, :] @ W1^T + b     (no relu), n in [0, N)
// ---------------------------------------------------------------------------
__global__ void __launch_bounds__(NT, 1)
build_u_kernel(const float* __restrict__ x,
               const float* __restrict__ W,
               const float* __restrict__ bias,
               int N)
{
    extern __shared__ __align__(1024) char smem[];
    const int tid  = threadIdx.x;
    const int lane = tid & 31;
    const int wid  = tid >> 5;
    const uint32_t sb = smem_u32(smem);
    const int n0 = blockIdx.x << 7;

    stage_w(smem, K1_WHI, W, tid);     // W1 = W[:, 0:64]

    // A tile: x rows n0..n0+127 (K = 64)
    {
        const int g = tid & 7, k0 = g << 3;
        const int r0 = tid >> 3;
        #pragma unroll
        for (int i = 0; i < 2; ++i) {
            int r = r0 + (i << 6);
            float4 a, b;
            if (n0 + r < N) {
                const float4* s = (const float4*)(x + ((size_t)(n0 + r) << 6) + k0);
                a = s[0]; b = s[1];
            } else {
                a = make_float4(0.f, 0.f, 0.f, 0.f); b = a;
            }
            store_row8(smem, K1_AHI, r, k0, a, b);
        }
    }
    __syncthreads();

    const int wm = wid & 3;
    const int wn = wid >> 2;
    const uint32_t a_off = (uint32_t)((lane & 15) * LDA_B + ((lane >> 4) << 4));
    const uint32_t b_off = (uint32_t)(((lane & 7) + ((lane >> 4) << 3)) * LDA_B
                                      + (((lane >> 3) & 1) << 4));
    const uint32_t pa = sb + K1_AHI + (uint32_t)(wm * 32 * LDA_B) + a_off;
    const uint32_t pb = sb + K1_WHI + (uint32_t)(wn * 32 * LDA_B) + b_off;

    float acc[2][4][4];
    #pragma unroll
    for (int mf = 0; mf < 2; ++mf)
        #pragma unroll
        for (int nf = 0; nf < 4; ++nf)
            #pragma unroll
            for (int v = 0; v < 4; ++v) acc[mf][nf][v] = 0.f;

    #pragma unroll
    for (int ks = 0; ks < 4; ++ks) {
        uint32_t ah[2][4], al[2][4], bh[2][4], blo[2][4];
        #pragma unroll
        for (int mf = 0; mf < 2; ++mf) {
            const uint32_t ao = pa + (uint32_t)(mf * 16 * LDA_B + ks * 32);
            LDSM4(ah[mf], ao);
            LDSM4(al[mf], ao + TILE_B);
        }
        LDSM4(bh[0],  pb + (uint32_t)(ks * 32));
        LDSM4(bh[1],  pb + (uint32_t)(16 * LDA_B + ks * 32));
        LDSM4(blo[0], pb + (uint32_t)(TILE_B + ks * 32));
        LDSM4(blo[1], pb + (uint32_t)(TILE_B + 16 * LDA_B + ks * 32));
        #pragma unroll
        for (int mf = 0; mf < 2; ++mf)
            #pragma unroll
            for (int nf = 0; nf < 4; ++nf) {
                const uint32_t b0h = bh[nf >> 1][(nf & 1) * 2];
                const uint32_t b1h = bh[nf >> 1][(nf & 1) * 2 + 1];
                MMA_BF16(acc[mf][nf], ah[mf], b0h, b1h);
                MMA_BF16(acc[mf][nf], al[mf], b0h, b1h);
                MMA_BF16(acc[mf][nf], ah[mf],
                         blo[nf >> 1][(nf & 1) * 2],
                         blo[nf >> 1][(nf & 1) * 2 + 1]);
            }
    }

    const int col0 = wn * 32 + 2 * (lane & 3);
    const int r0 = n0 + wm * 32 + (lane >> 2);
    #pragma unroll
    for (int mf = 0; mf < 2; ++mf) {
        const int ra  = r0 + mf * 16;
        const int rbw = ra + 8;
        #pragma unroll
        for (int nf = 0; nf < 4; ++nf) {
            const int c = col0 + nf * 8;
            const float b0 = bias[c], b1 = bias[c + 1];
            if (ra < N) {
                float2 v = make_float2(acc[mf][nf][0] + b0, acc[mf][nf][1] + b1);
                *(float2*)(U_buf + (size_t)ra * 128 + c) = v;
            }
            if (rbw < N) {
                float2 v = make_float2(acc[mf][nf][2] + b0, acc[mf][nf][3] + b1);
                *(float2*)(U_buf + (size_t)rbw * 128 + c) = v;
            }
        }
    }
}

// ---------------------------------------------------------------------------
// Kernel 2: out[e, :] = relu(ea[e, :] @ W2^T + U[row[e], :])
// ---------------------------------------------------------------------------
__global__ void __launch_bounds__(NT, 1)
edge_enc_kernel(const float* __restrict__ ea,
                const void*  __restrict__ eidx_raw,
                const float* __restrict__ W,
                float* __restrict__ out,
                int E)
{
    extern __shared__ __align__(1024) char smem[];
    const int tid  = threadIdx.x;
    const int lane = tid & 31;
    const int wid  = tid >> 5;
    const uint32_t sb = smem_u32(smem);

    // index dtype sniff: int64 entries (values < 50000) have zero high words
    const int* e32 = (const int*)eidx_raw;
    const long long* e64 = (const long long*)eidx_raw;
    const bool is64 = ((e32[1] | e32[3] | e32[5] | e32[7]) == 0);

    stage_w(smem, K2_WHI, W + 64, tid);   // W2 = W[:, 64:128]

    const int g  = tid & 7, k0 = g << 3;
    const int r0s = tid >> 3;             // staging row base 0..63

    const int wm = wid & 3;
    const int wn = wid >> 2;
    const uint32_t a_off = (uint32_t)((lane & 15) * LDA_B + ((lane >> 4) << 4));
    const uint32_t b_off = (uint32_t)(((lane & 7) + ((lane >> 4) << 3)) * LDA_B
                                      + (((lane >> 3) & 1) << 4));
    const uint32_t aA = (uint32_t)(wm * 32 * LDA_B) + a_off;
    const uint32_t pb = sb + K2_WHI + (uint32_t)(wn * 32 * LDA_B) + b_off;

    const int col0 = wn * 32 + 2 * (lane & 3);
    const int ntiles = (E + 127) >> 7;

    // prefetch first tile (edge_attr only; 16 floats/thread)
    float4 va[2], vb[2];
    if (blockIdx.x < ntiles) {
        const int e0 = blockIdx.x << 7;
        #pragma unroll
        for (int i = 0; i < 2; ++i) {
            int e = e0 + r0s + (i << 6);
            if (e < E) {
                const float4* s = (const float4*)(ea + ((size_t)e << 6) + k0);
                va[i] = s[0]; vb[i] = s[1];
            } else {
                va[i] = make_float4(0.f, 0.f, 0.f, 0.f); vb[i] = va[i];
            }
        }
    }

    int p = 0;
    for (int t = blockIdx.x; t < ntiles; t += gridDim.x) {
        const int e0 = t << 7;

        // stage current tile
        #pragma unroll
        for (int i = 0; i < 2; ++i)
            store_row8(smem, K2_AHI(p), r0s + (i << 6), k0, va[i], vb[i]);
        __syncthreads();

        // prefetch next tile's edge_attr
        const int tn = t + gridDim.x;
        if (tn < ntiles) {
            const int en = tn << 7;
            #pragma unroll
            for (int i = 0; i < 2; ++i) {
                int e = en + r0s + (i << 6);
                if (e < E) {
                    const float4* s = (const float4*)(ea + ((size_t)e << 6) + k0);
                    va[i] = s[0]; vb[i] = s[1];
                } else {
                    va[i] = make_float4(0.f, 0.f, 0.f, 0.f); vb[i] = va[i];
                }
            }
        }

        // ---- fused MMA over K=64: D = Ah*Wh^T + Al*Wh^T + Ah*Wl^T -----------
        float acc[2][4][4];
        #pragma unroll
        for (int mf = 0; mf < 2; ++mf)
            #pragma unroll
            for (int nf = 0; nf < 4; ++nf)
                #pragma unroll
                for (int v = 0; v < 4; ++v) acc[mf][nf][v] = 0.f;

        const uint32_t pa = sb + (uint32_t)K2_AHI(p) + aA;
        #pragma unroll
        for (int ks = 0; ks < 4; ++ks) {
            uint32_t ah[2][4], al[2][4], bh[2][4], blo[2][4];
            #pragma unroll
            for (int mf = 0; mf < 2; ++mf) {
                const uint32_t ao = pa + (uint32_t)(mf * 16 * LDA_B + ks * 32);
                LDSM4(ah[mf], ao);
                LDSM4(al[mf], ao + TILE_B);
            }
            LDSM4(bh[0],  pb + (uint32_t)(ks * 32));
            LDSM4(bh[1],  pb + (uint32_t)(16 * LDA_B + ks * 32));
            LDSM4(blo[0], pb + (uint32_t)(TILE_B + ks * 32));
            LDSM4(blo[1], pb + (uint32_t)(TILE_B + 16 * LDA_B + ks * 32));
            #pragma unroll
            for (int mf = 0; mf < 2; ++mf)
                #pragma unroll
                for (int nf = 0; nf < 4; ++nf) {
                    const uint32_t b0h = bh[nf >> 1][(nf & 1) * 2];
                    const uint32_t b1h = bh[nf >> 1][(nf & 1) * 2 + 1];
                    MMA_BF16(acc[mf][nf], ah[mf], b0h, b1h);
                    MMA_BF16(acc[mf][nf], al[mf], b0h, b1h);
                    MMA_BF16(acc[mf][nf], ah[mf],
                             blo[nf >> 1][(nf & 1) * 2],
                             blo[nf >> 1][(nf & 1) * 2 + 1]);
                }
        }

        // ---- epilogue: gather U[row[e]] from L2, add, relu, store -----------
        const int rr = e0 + wm * 32 + (lane >> 2);
        #pragma unroll
        for (int mf = 0; mf < 2; ++mf) {
            const int ra  = rr + mf * 16;
            const int rbw = ra + 8;
            const bool oka = ra < E, okb = rbw < E;
            size_t ria = 0, rib = 0;
            if (oka) ria = (size_t)(is64 ? e64[ra]  : (long long)e32[ra]);
            if (okb) rib = (size_t)(is64 ? e64[rbw] : (long long)e32[rbw]);
            const float* Ua = U_buf + ria * 128;
            const float* Ub = U_buf + rib * 128;
            float2 ua[4], ub[4];
            #pragma unroll
            for (int nf = 0; nf < 4; ++nf) {
                const int c = col0 + nf * 8;
                if (oka) ua[nf] = *(const float2*)(Ua + c);
                if (okb) ub[nf] = *(const float2*)(Ub + c);
            }
            #pragma unroll
            for (int nf = 0; nf < 4; ++nf) {
                const int c = col0 + nf * 8;
                if (oka) {
                    float2 v;
                    v.x = fmaxf(acc[mf][nf][0] + ua[nf].x, 0.f);
                    v.y = fmaxf(acc[mf][nf][1] + ua[nf].y, 0.f);
                    *(float2*)(out + (size_t)ra * 128 + c) = v;
                }
                if (okb) {
                    float2 v;
                    v.x = fmaxf(acc[mf][nf][2] + ub[nf].x, 0.f);
                    v.y = fmaxf(acc[mf][nf][3] + ub[nf].y, 0.f);
                    *(float2*)(out + (size_t)rbw * 128 + c) = v;
                }
            }
        }
        p ^= 1;
        // no trailing sync: next iter writes the other buffer; the sync above
        // already proved all warps finished reading it.
    }
}

extern "C" void kernel_launch(void* const* d_in, const int* in_sizes, int n_in,
                              void* d_out, int out_size) {
    const float* x  = (const float*)d_in[0];
    const float* ea = (const float*)d_in[1];
    const void*  ei = (const void*)d_in[2];
    const float* W  = (const float*)d_in[3];
    const float* b  = (const float*)d_in[4];
    float* out = (float*)d_out;

    const int N = in_sizes[0] / 64;   // x is [N, 64]
    const int E = in_sizes[1] / 64;   // edge_attr is [E, 64]
    if (E <= 0 || N <= 0) return;

    cudaFuncSetAttribute(build_u_kernel,
                         cudaFuncAttributeMaxDynamicSharedMemorySize, K1_SMEM);
    cudaFuncSetAttribute(edge_enc_kernel,
                         cudaFuncAttributeMaxDynamicSharedMemorySize, K2_SMEM);

    build_u_kernel<<<(N + 127) / 128, NT, K1_SMEM>>>(x, W, b, N);
    edge_enc_kernel<<<148, NT, K2_SMEM>>>(ea, ei, W, out, E);
}

// round 15
// speedup vs baseline: 2.7526x; 1.3602x over previous
#include <cuda_runtime.h>
#include <cstdint>

// ---------------------------------------------------------------------------
// DirectedEdgeEncoder: out[E,128] = relu(concat(x[row[e]], edge_attr[e]) @ W^T + b)
// Split: U = x @ W1^T + b  (N=50k rows, tiny GEMM, L2-resident scratch)
//        out[e] = relu(ea[e] @ W2^T + U[row[e]])   (K=64 GEMM + coalesced gather)
// mma.sync m16n8k16 bf16 (sm_103-portable), fp32 accum, 3-term hi/lo split:
//   D = Ah*Wh + Al*Wh + Ah*Wl   (drops lo*lo, ~1e-5 rel)
// Epilogue routes acc through an SMEM staging tile so the U gather and the
// output stores are warp-coalesced full rows (4 wavefronts/row instead of ~8
// wavefronts per fragment instruction).
// ---------------------------------------------------------------------------

#define NT 512
#define LDA_B 144                 // bytes per bf16 tile row (64 bf16 = 128B + 16 pad)
#define TILE_B (128 * LDA_B)      // 18432 B per operand tile (128 rows x 64 k)
#define LDA_OUT 136               // fp32 staging row pitch (128 + 8 pad floats)

// kernel-2 smem: A double buffer (hi+lo) + static W2 (hi+lo) + fp32 out staging
#define K2_AHI(p) ((p) * 2 * TILE_B)
#define K2_WHI    (4 * TILE_B)
#define K2_OUT    (6 * TILE_B)                    // 110592
#define K2_SMEM   (K2_OUT + 128 * LDA_OUT * 4)    // 110592 + 69632 = 180224 B
// kernel-1 smem: single A (hi+lo) + W1 (hi+lo)
#define K1_AHI 0
#define K1_WHI (2 * TILE_B)
#define K1_SMEM (4 * TILE_B)      // 73728 B

#define U_MAX_ROWS 65536
__device__ float U_buf[(size_t)U_MAX_ROWS * 128];

static __device__ __forceinline__ uint32_t smem_u32(const void* p) {
    uint32_t a;
    asm("{ .reg .u64 t; cvta.to.shared.u64 t, %1; cvt.u32.u64 %0, t; }"
        : "=r"(a) : "l"(p));
    return a;
}

// pack two f32 -> bf16x2 (RN): 'e' low half (even k), 'o' high half (odd k)
static __device__ __forceinline__ uint32_t pack_bf16x2(float e, float o) {
    uint32_t r;
    asm("cvt.rn.bf16x2.f32 %0, %1, %2;" : "=r"(r) : "f"(o), "f"(e));
    return r;
}

// split (e,o) into bf16 hi word + bf16 lo (residual) word
static __device__ __forceinline__ void cvt2(float e, float o,
                                            uint32_t& hw, uint32_t& lw) {
    hw = pack_bf16x2(e, o);
    float fe = __uint_as_float(hw << 16);
    float fo = __uint_as_float(hw & 0xFFFF0000u);
    lw = pack_bf16x2(e - fe, o - fo);
}

#define LDSM4(r, addr)                                                        \
    asm volatile("ldmatrix.sync.aligned.m8n8.x4.shared.b16 {%0,%1,%2,%3}, [%4];" \
                 : "=r"((r)[0]), "=r"((r)[1]), "=r"((r)[2]), "=r"((r)[3])     \
                 : "r"(addr))

#define MMA_BF16(d, a, b0, b1)                                                \
    asm volatile("mma.sync.aligned.m16n8k16.row.col.f32.bf16.bf16.f32 "       \
                 "{%0,%1,%2,%3}, {%4,%5,%6,%7}, {%8,%9}, {%0,%1,%2,%3};"      \
                 : "+f"((d)[0]), "+f"((d)[1]), "+f"((d)[2]), "+f"((d)[3])     \
                 : "r"((a)[0]), "r"((a)[1]), "r"((a)[2]), "r"((a)[3]),        \
                   "r"(b0), "r"(b1))

// convert 2 float4 (8 consecutive k-values of one row) -> bf16 hi/lo in SMEM
static __device__ __forceinline__ void store_row8(char* smem, int hi_off,
                                                  int r, int k0,
                                                  float4 a, float4 b) {
    uint32_t h[4], l[4];
    cvt2(a.x, a.y, h[0], l[0]);
    cvt2(a.z, a.w, h[1], l[1]);
    cvt2(b.x, b.y, h[2], l[2]);
    cvt2(b.z, b.w, h[3], l[3]);
    int off = r * LDA_B + (k0 << 1);
    *(uint4*)(smem + hi_off + off) = make_uint4(h[0], h[1], h[2], h[3]);
    *(uint4*)(smem + hi_off + TILE_B + off) = make_uint4(l[0], l[1], l[2], l[3]);
}

// stage a [128 x 64] fp32 W slice (row stride 128 floats) as bf16 hi/lo tiles
static __device__ __forceinline__ void stage_w(char* smem, int hi_off,
                                               const float* __restrict__ Wsl,
                                               int tid) {
    const int g = tid & 7, k0 = g << 3;
    const int r0 = tid >> 3;           // 0..63
    #pragma unroll
    for (int i = 0; i < 2; ++i) {
        int r = r0 + (i << 6);
        const float4* s = (const float4*)(Wsl + r * 128 + k0);
        store_row8(smem, hi_off, r, k0, s[0], s[1]);
    }
}

// ---------------------------------------------------------------------------
// Kernel 1: U[n, :] = x[n, :] @ W1^T + b     (no relu), n in [0, N)
// ---------------------------------------------------------------------------
__global__ void __launch_bounds__(NT, 1)
build_u_kernel(const float* __restrict__ x,
               const float* __restrict__ W,
               const float* __restrict__ bias,
               int N)
{
    extern __shared__ __align__(1024) char smem[];
    const int tid  = threadIdx.x;
    const int lane = tid & 31;
    const int wid  = tid >> 5;
    const uint32_t sb = smem_u32(smem);
    const int n0 = blockIdx.x << 7;

    stage_w(smem, K1_WHI, W, tid);     // W1 = W[:, 0:64]

    // A tile: x rows n0..n0+127 (K = 64)
    {
        const int g = tid & 7, k0 = g << 3;
        const int r0 = tid >> 3;
        #pragma unroll
        for (int i = 0; i < 2; ++i) {
            int r = r0 + (i << 6);
            float4 a, b;
            if (n0 + r < N) {
                const float4* s = (const float4*)(x + ((size_t)(n0 + r) << 6) + k0);
                a = s[0]; b = s[1];
            } else {
                a = make_float4(0.f, 0.f, 0.f, 0.f); b = a;
            }
            store_row8(smem, K1_AHI, r, k0, a, b);
        }
    }
    __syncthreads();

    const int wm = wid & 3;
    const int wn = wid >> 2;
    const uint32_t a_off = (uint32_t)((lane & 15) * LDA_B + ((lane >> 4) << 4));
    const uint32_t b_off = (uint32_t)(((lane & 7) + ((lane >> 4) << 3)) * LDA_B
                                      + (((lane >> 3) & 1) << 4));
    const uint32_t pa = sb + K1_AHI + (uint32_t)(wm * 32 * LDA_B) + a_off;
    const uint32_t pb = sb + K1_WHI + (uint32_t)(wn * 32 * LDA_B) + b_off;

    float acc[2][4][4];
    #pragma unroll
    for (int mf = 0; mf < 2; ++mf)
        #pragma unroll
        for (int nf = 0; nf < 4; ++nf)
            #pragma unroll
            for (int v = 0; v < 4; ++v) acc[mf][nf][v] = 0.f;

    #pragma unroll
    for (int ks = 0; ks < 4; ++ks) {
        uint32_t ah[2][4], al[2][4], bh[2][4], blo[2][4];
        #pragma unroll
        for (int mf = 0; mf < 2; ++mf) {
            const uint32_t ao = pa + (uint32_t)(mf * 16 * LDA_B + ks * 32);
            LDSM4(ah[mf], ao);
            LDSM4(al[mf], ao + TILE_B);
        }
        LDSM4(bh[0],  pb + (uint32_t)(ks * 32));
        LDSM4(bh[1],  pb + (uint32_t)(16 * LDA_B + ks * 32));
        LDSM4(blo[0], pb + (uint32_t)(TILE_B + ks * 32));
        LDSM4(blo[1], pb + (uint32_t)(TILE_B + 16 * LDA_B + ks * 32));
        #pragma unroll
        for (int mf = 0; mf < 2; ++mf)
            #pragma unroll
            for (int nf = 0; nf < 4; ++nf) {
                const uint32_t b0h = bh[nf >> 1][(nf & 1) * 2];
                const uint32_t b1h = bh[nf >> 1][(nf & 1) * 2 + 1];
                MMA_BF16(acc[mf][nf], ah[mf], b0h, b1h);
                MMA_BF16(acc[mf][nf], al[mf], b0h, b1h);
                MMA_BF16(acc[mf][nf], ah[mf],
                         blo[nf >> 1][(nf & 1) * 2],
                         blo[nf >> 1][(nf & 1) * 2 + 1]);
            }
    }

    const int col0 = wn * 32 + 2 * (lane & 3);
    const int r0 = n0 + wm * 32 + (lane >> 2);
    #pragma unroll
    for (int mf = 0; mf < 2; ++mf) {
        const int ra  = r0 + mf * 16;
        const int rbw = ra + 8;
        #pragma unroll
        for (int nf = 0; nf < 4; ++nf) {
            const int c = col0 + nf * 8;
            const float b0 = bias[c], b1 = bias[c + 1];
            if (ra < N) {
                float2 v = make_float2(acc[mf][nf][0] + b0, acc[mf][nf][1] + b1);
                *(float2*)(U_buf + (size_t)ra * 128 + c) = v;
            }
            if (rbw < N) {
                float2 v = make_float2(acc[mf][nf][2] + b0, acc[mf][nf][3] + b1);
                *(float2*)(U_buf + (size_t)rbw * 128 + c) = v;
            }
        }
    }
}

// ---------------------------------------------------------------------------
// Kernel 2: out[e, :] = relu(ea[e, :] @ W2^T + U[row[e], :])
// ---------------------------------------------------------------------------
__global__ void __launch_bounds__(NT, 1)
edge_enc_kernel(const float* __restrict__ ea,
                const void*  __restrict__ eidx_raw,
                const float* __restrict__ W,
                float* __restrict__ out,
                int E)
{
    extern __shared__ __align__(1024) char smem[];
    const int tid  = threadIdx.x;
    const int lane = tid & 31;
    const int wid  = tid >> 5;
    const uint32_t sb = smem_u32(smem);
    float* stg = (float*)(smem + K2_OUT);

    // index dtype sniff: int64 entries (values < 50000) have zero high words
    const int* e32 = (const int*)eidx_raw;
    const long long* e64 = (const long long*)eidx_raw;
    const bool is64 = ((e32[1] | e32[3] | e32[5] | e32[7]) == 0);

    stage_w(smem, K2_WHI, W + 64, tid);   // W2 = W[:, 64:128]

    const int g  = tid & 7, k0 = g << 3;
    const int r0s = tid >> 3;             // staging row base 0..63

    const int wm = wid & 3;
    const int wn = wid >> 2;
    const uint32_t a_off = (uint32_t)((lane & 15) * LDA_B + ((lane >> 4) << 4));
    const uint32_t b_off = (uint32_t)(((lane & 7) + ((lane >> 4) << 3)) * LDA_B
                                      + (((lane >> 3) & 1) << 4));
    const uint32_t aA = (uint32_t)(wm * 32 * LDA_B) + a_off;
    const uint32_t pb = sb + K2_WHI + (uint32_t)(wn * 32 * LDA_B) + b_off;

    const int col0 = wn * 32 + 2 * (lane & 3);
    const int ntiles = (E + 127) >> 7;

    // prefetch first tile (edge_attr only; 16 floats/thread)
    float4 va[2], vb[2];
    if (blockIdx.x < ntiles) {
        const int e0 = blockIdx.x << 7;
        #pragma unroll
        for (int i = 0; i < 2; ++i) {
            int e = e0 + r0s + (i << 6);
            if (e < E) {
                const float4* s = (const float4*)(ea + ((size_t)e << 6) + k0);
                va[i] = s[0]; vb[i] = s[1];
            } else {
                va[i] = make_float4(0.f, 0.f, 0.f, 0.f); vb[i] = va[i];
            }
        }
    }

    int p = 0;
    for (int t = blockIdx.x; t < ntiles; t += gridDim.x) {
        const int e0 = t << 7;

        // stage current tile
        #pragma unroll
        for (int i = 0; i < 2; ++i)
            store_row8(smem, K2_AHI(p), r0s + (i << 6), k0, va[i], vb[i]);
        __syncthreads();

        // prefetch next tile's edge_attr
        const int tn = t + gridDim.x;
        if (tn < ntiles) {
            const int en = tn << 7;
            #pragma unroll
            for (int i = 0; i < 2; ++i) {
                int e = en + r0s + (i << 6);
                if (e < E) {
                    const float4* s = (const float4*)(ea + ((size_t)e << 6) + k0);
                    va[i] = s[0]; vb[i] = s[1];
                } else {
                    va[i] = make_float4(0.f, 0.f, 0.f, 0.f); vb[i] = va[i];
                }
            }
        }

        // ---- fused MMA over K=64: D = Ah*Wh^T + Al*Wh^T + Ah*Wl^T -----------
        float acc[2][4][4];
        #pragma unroll
        for (int mf = 0; mf < 2; ++mf)
            #pragma unroll
            for (int nf = 0; nf < 4; ++nf)
                #pragma unroll
                for (int v = 0; v < 4; ++v) acc[mf][nf][v] = 0.f;

        const uint32_t pa = sb + (uint32_t)K2_AHI(p) + aA;
        #pragma unroll
        for (int ks = 0; ks < 4; ++ks) {
            uint32_t ah[2][4], al[2][4], bh[2][4], blo[2][4];
            #pragma unroll
            for (int mf = 0; mf < 2; ++mf) {
                const uint32_t ao = pa + (uint32_t)(mf * 16 * LDA_B + ks * 32);
                LDSM4(ah[mf], ao);
                LDSM4(al[mf], ao + TILE_B);
            }
            LDSM4(bh[0],  pb + (uint32_t)(ks * 32));
            LDSM4(bh[1],  pb + (uint32_t)(16 * LDA_B + ks * 32));
            LDSM4(blo[0], pb + (uint32_t)(TILE_B + ks * 32));
            LDSM4(blo[1], pb + (uint32_t)(TILE_B + 16 * LDA_B + ks * 32));
            #pragma unroll
            for (int mf = 0; mf < 2; ++mf)
                #pragma unroll
                for (int nf = 0; nf < 4; ++nf) {
                    const uint32_t b0h = bh[nf >> 1][(nf & 1) * 2];
                    const uint32_t b1h = bh[nf >> 1][(nf & 1) * 2 + 1];
                    MMA_BF16(acc[mf][nf], ah[mf], b0h, b1h);
                    MMA_BF16(acc[mf][nf], al[mf], b0h, b1h);
                    MMA_BF16(acc[mf][nf], ah[mf],
                             blo[nf >> 1][(nf & 1) * 2],
                             blo[nf >> 1][(nf & 1) * 2 + 1]);
                }
        }

        // ---- dump acc fragments to fp32 staging tile (crossbar, cheap) ------
        {
            const int rl0 = wm * 32 + (lane >> 2);
            #pragma unroll
            for (int mf = 0; mf < 2; ++mf) {
                float* r0p = stg + (rl0 + mf * 16) * LDA_OUT;
                float* r1p = r0p + 8 * LDA_OUT;
                #pragma unroll
                for (int nf = 0; nf < 4; ++nf) {
                    const int c = col0 + nf * 8;
                    *(float2*)(r0p + c) = make_float2(acc[mf][nf][0], acc[mf][nf][1]);
                    *(float2*)(r1p + c) = make_float2(acc[mf][nf][2], acc[mf][nf][3]);
                }
            }
        }
        __syncthreads();

        // ---- coalesced epilogue: warp w owns rows 8w..8w+7 -------------------
        {
            const int wr0 = wid << 3;
            long long ri[8];
            #pragma unroll
            for (int i = 0; i < 8; ++i) {
                const int e = e0 + wr0 + i;
                ri[i] = (e < E) ? (is64 ? e64[e] : (long long)e32[e]) : -1;
            }
            float4 u[8], a[8];
            #pragma unroll
            for (int i = 0; i < 8; ++i)
                if (ri[i] >= 0)
                    u[i] = *(const float4*)(U_buf + ((size_t)ri[i] << 7) + (lane << 2));
            #pragma unroll
            for (int i = 0; i < 8; ++i)
                a[i] = *(const float4*)(stg + (wr0 + i) * LDA_OUT + (lane << 2));
            #pragma unroll
            for (int i = 0; i < 8; ++i) {
                if (ri[i] >= 0) {
                    float4 v;
                    v.x = fmaxf(a[i].x + u[i].x, 0.f);
                    v.y = fmaxf(a[i].y + u[i].y, 0.f);
                    v.z = fmaxf(a[i].z + u[i].z, 0.f);
                    v.w = fmaxf(a[i].w + u[i].w, 0.f);
                    *(float4*)(out + ((size_t)(e0 + wr0 + i) << 7) + (lane << 2)) = v;
                }
            }
        }
        p ^= 1;
        // next iteration stages the OTHER A buffer, then hits a barrier before
        // anyone re-writes the staging tile — no trailing sync needed.
    }
}

extern "C" void kernel_launch(void* const* d_in, const int* in_sizes, int n_in,
                              void* d_out, int out_size) {
    const float* x  = (const float*)d_in[0];
    const float* ea = (const float*)d_in[1];
    const void*  ei = (const void*)d_in[2];
    const float* W  = (const float*)d_in[3];
    const float* b  = (const float*)d_in[4];
    float* out = (float*)d_out;

    const int N = in_sizes[0] / 64;   // x is [N, 64]
    const int E = in_sizes[1] / 64;   // edge_attr is [E, 64]
    if (E <= 0 || N <= 0) return;

    cudaFuncSetAttribute(build_u_kernel,
                         cudaFuncAttributeMaxDynamicSharedMemorySize, K1_SMEM);
    cudaFuncSetAttribute(edge_enc_kernel,
                         cudaFuncAttributeMaxDynamicSharedMemorySize, K2_SMEM);

    build_u_kernel<<<(N + 127) / 128, NT, K1_SMEM>>>(x, W, b, N);
    edge_enc_kernel<<<148, NT, K2_SMEM>>>(ea, ei, W, out, E);
}